// round 2
// baseline (speedup 1.0000x reference)
#include <cuda_runtime.h>
#include <cuda_bf16.h>
#include <math.h>

// Problem constants
#define BSZ 2
#define SEQ 2048
#define DIM 4096
#define NH 32
#define NKV 8
#define HD 128
#define TOKENS (BSZ*SEQ)   // 4096

// Scratch (device globals — no allocation allowed)
__device__ float g_xq[(size_t)TOKENS * NH * HD];    // 4096 x 4096
__device__ float g_xk[(size_t)TOKENS * NKV * HD];   // 4096 x 1024
__device__ float g_xv[(size_t)TOKENS * NKV * HD];   // 4096 x 1024
__device__ float g_attn[(size_t)TOKENS * NH * HD];  // 4096 x 4096

// ---------------------------------------------------------------------------
// Tiled fp32 SGEMM: C[M,N] = A[M,K] @ B[K,N], all row-major.
// BM=BN=128, BK=8, 256 threads, 8x8 per-thread microtile.
// Dims assumed multiples of 128 / 8 (true here: M=4096, K=4096, N in {1024,4096}).
// ---------------------------------------------------------------------------
__global__ __launch_bounds__(256) void sgemm_kernel(
    const float* __restrict__ A, const float* __restrict__ B,
    float* __restrict__ C, int M, int N, int K)
{
    constexpr int BM = 128, BN = 128, BK = 8, TM = 8, TN = 8;
    __shared__ float As[BK][BM];
    __shared__ float Bs[BK][BN];

    const int tid = threadIdx.x;
    const int bm = blockIdx.y * BM;
    const int bn = blockIdx.x * BN;
    const int tx = tid % (BN / TN);   // 0..15
    const int ty = tid / (BN / TN);   // 0..15

    float acc[TM][TN];
    #pragma unroll
    for (int i = 0; i < TM; i++)
        #pragma unroll
        for (int j = 0; j < TN; j++) acc[i][j] = 0.f;

    const int aRow = tid >> 1;          // 0..127
    const int aCol = (tid & 1) * 4;     // 0 or 4
    const int bRow = tid >> 5;          // 0..7
    const int bCol = (tid & 31) * 4;    // 0..124

    for (int k0 = 0; k0 < K; k0 += BK) {
        float4 av = *(const float4*)&A[(size_t)(bm + aRow) * K + k0 + aCol];
        As[aCol + 0][aRow] = av.x;
        As[aCol + 1][aRow] = av.y;
        As[aCol + 2][aRow] = av.z;
        As[aCol + 3][aRow] = av.w;
        float4 bv = *(const float4*)&B[(size_t)(k0 + bRow) * N + bn + bCol];
        *(float4*)&Bs[bRow][bCol] = bv;
        __syncthreads();

        #pragma unroll
        for (int k = 0; k < BK; k++) {
            float af[TM], bf[TN];
            float4 a0 = *(const float4*)&As[k][ty * TM];
            float4 a1 = *(const float4*)&As[k][ty * TM + 4];
            af[0]=a0.x; af[1]=a0.y; af[2]=a0.z; af[3]=a0.w;
            af[4]=a1.x; af[5]=a1.y; af[6]=a1.z; af[7]=a1.w;
            float4 b0 = *(const float4*)&Bs[k][tx * TN];
            float4 b1 = *(const float4*)&Bs[k][tx * TN + 4];
            bf[0]=b0.x; bf[1]=b0.y; bf[2]=b0.z; bf[3]=b0.w;
            bf[4]=b1.x; bf[5]=b1.y; bf[6]=b1.z; bf[7]=b1.w;
            #pragma unroll
            for (int i = 0; i < TM; i++)
                #pragma unroll
                for (int j = 0; j < TN; j++)
                    acc[i][j] += af[i] * bf[j];
        }
        __syncthreads();
    }

    #pragma unroll
    for (int i = 0; i < TM; i++) {
        #pragma unroll
        for (int j = 0; j < TN; j += 4) {
            float4 v = make_float4(acc[i][j], acc[i][j+1], acc[i][j+2], acc[i][j+3]);
            *(float4*)&C[(size_t)(bm + ty * TM + i) * N + bn + tx * TN + j] = v;
        }
    }
}

// ---------------------------------------------------------------------------
// RoPE: in-place on [TOKENS, H, 128] tensor. One thread per (token, head, pair).
// ---------------------------------------------------------------------------
__global__ void rope_kernel(float* __restrict__ t,
                            const float* __restrict__ fc,
                            const float* __restrict__ fs, int H, int total)
{
    int i = blockIdx.x * blockDim.x + threadIdx.x;
    if (i >= total) return;
    int half = i & 63;              // 0..63
    int h    = (i >> 6) % H;
    int tok  = i / (64 * H);
    int s    = tok & (SEQ - 1);     // position within sequence
    float c  = fc[s * 64 + half];
    float sn = fs[s * 64 + half];
    float* p = t + (((size_t)tok * H + h) * HD) + 2 * half;
    float a = p[0], b = p[1];
    p[0] = a * c - b * sn;
    p[1] = a * sn + b * c;
}

// ---------------------------------------------------------------------------
// Causal flash attention, fp32, GQA (4 q-heads per kv-head).
// grid: (SEQ/64, NH, BSZ), 256 threads.
// Thread (row = tid/4 of 64 q rows, c4 = tid%4 dim-chunk of 32).
// Q in registers; K/V tiles (32 x 128) staged in smem.
// ---------------------------------------------------------------------------
__global__ __launch_bounds__(256) void flash_kernel(
    const float* __restrict__ q, const float* __restrict__ k,
    const float* __restrict__ v, float* __restrict__ o)
{
    constexpr int BM = 64, BN = 32, D = HD;
    __shared__ float Ks[BN][D];
    __shared__ float Vs[BN][D];

    const int m0 = blockIdx.x * BM;
    const int h  = blockIdx.y;
    const int b  = blockIdx.z;
    const int kh = h >> 2;
    const int tid = threadIdx.x;
    const int row = tid >> 2;     // 0..63
    const int c4  = tid & 3;      // dim chunk of 32
    const int qrow = m0 + row;

    // Q row chunk -> registers
    float qreg[32];
    {
        const float* qp = q + (((size_t)b * SEQ + qrow) * NH + h) * D + c4 * 32;
        #pragma unroll
        for (int d = 0; d < 32; d += 4) {
            float4 t = *(const float4*)(qp + d);
            qreg[d] = t.x; qreg[d+1] = t.y; qreg[d+2] = t.z; qreg[d+3] = t.w;
        }
    }

    float acc[32];
    #pragma unroll
    for (int d = 0; d < 32; d++) acc[d] = 0.f;
    float m = -INFINITY, l = 0.f;
    const float scale = 0.08838834764831845f; // 1/sqrt(128)

    for (int j0 = 0; j0 < m0 + BM; j0 += BN) {
        // load K,V tile: 32x128 floats each; thread loads 16 consecutive floats
        {
            int base = tid * 16;
            int tr = base >> 7, tc = base & 127;
            const float* kp = k + (((size_t)b * SEQ + j0 + tr) * NKV + kh) * D + tc;
            const float* vp = v + (((size_t)b * SEQ + j0 + tr) * NKV + kh) * D + tc;
            #pragma unroll
            for (int u = 0; u < 16; u += 4) {
                *(float4*)&Ks[tr][tc + u] = *(const float4*)(kp + u);
                *(float4*)&Vs[tr][tc + u] = *(const float4*)(vp + u);
            }
        }
        __syncthreads();

        float s[BN];
        float tile_max = -INFINITY;
        #pragma unroll
        for (int j = 0; j < BN; j++) {
            float p = 0.f;
            const float4* kr = (const float4*)&Ks[j][c4 * 32];
            #pragma unroll
            for (int d4 = 0; d4 < 8; d4++) {
                float4 kv = kr[d4];
                p += qreg[4*d4+0]*kv.x + qreg[4*d4+1]*kv.y
                   + qreg[4*d4+2]*kv.z + qreg[4*d4+3]*kv.w;
            }
            p += __shfl_xor_sync(0xffffffffu, p, 1);
            p += __shfl_xor_sync(0xffffffffu, p, 2);
            p *= scale;
            if (j0 + j > qrow) p = -INFINITY;
            s[j] = p;
            tile_max = fmaxf(tile_max, p);
        }

        float m_new = fmaxf(m, tile_max);
        float corr = __expf(m - m_new);
        l *= corr;
        #pragma unroll
        for (int d = 0; d < 32; d++) acc[d] *= corr;

        #pragma unroll
        for (int j = 0; j < BN; j++) {
            float p = __expf(s[j] - m_new);
            l += p;
            const float4* vr = (const float4*)&Vs[j][c4 * 32];
            #pragma unroll
            for (int d4 = 0; d4 < 8; d4++) {
                float4 vv = vr[d4];
                acc[4*d4+0] += p * vv.x;
                acc[4*d4+1] += p * vv.y;
                acc[4*d4+2] += p * vv.z;
                acc[4*d4+3] += p * vv.w;
            }
        }
        m = m_new;
        __syncthreads();
    }

    float inv = 1.f / l;
    float* op = o + (((size_t)b * SEQ + qrow) * NH + h) * D + c4 * 32;
    #pragma unroll
    for (int d = 0; d < 32; d += 4) {
        float4 t = make_float4(acc[d]*inv, acc[d+1]*inv, acc[d+2]*inv, acc[d+3]*inv);
        *(float4*)(op + d) = t;
    }
}

// ---------------------------------------------------------------------------
extern "C" void kernel_launch(void* const* d_in, const int* in_sizes, int n_in,
                              void* d_out, int out_size)
{
    const float* x  = (const float*)d_in[0];
    const float* wq = (const float*)d_in[1];
    const float* wk = (const float*)d_in[2];
    const float* wv = (const float*)d_in[3];
    const float* wo = (const float*)d_in[4];
    const float* fc = (const float*)d_in[7];
    const float* fs = (const float*)d_in[8];
    float* out = (float*)d_out;

    float *xq, *xk, *xv, *attn;
    cudaGetSymbolAddress((void**)&xq,   g_xq);
    cudaGetSymbolAddress((void**)&xk,   g_xk);
    cudaGetSymbolAddress((void**)&xv,   g_xv);
    cudaGetSymbolAddress((void**)&attn, g_attn);

    // QKV projections
    {
        dim3 gq(DIM / 128, TOKENS / 128);          // N=4096
        sgemm_kernel<<<gq, 256>>>(x, wq, xq, TOKENS, NH * HD, DIM);
        dim3 gk((NKV * HD) / 128, TOKENS / 128);   // N=1024
        sgemm_kernel<<<gk, 256>>>(x, wk, xk, TOKENS, NKV * HD, DIM);
        sgemm_kernel<<<gk, 256>>>(x, wv, xv, TOKENS, NKV * HD, DIM);
    }

    // RoPE on q and k
    {
        int tq = TOKENS * NH * 64;
        rope_kernel<<<(tq + 255) / 256, 256>>>(xq, fc, fs, NH, tq);
        int tk = TOKENS * NKV * 64;
        rope_kernel<<<(tk + 255) / 256, 256>>>(xk, fc, fs, NKV, tk);
    }

    // Causal flash attention (start_pos = 0, cache is zero => keys/values = xk/xv)
    {
        dim3 g(SEQ / 64, NH, BSZ);
        flash_kernel<<<g, 256>>>(xq, xk, xv, attn);
    }

    // Output projection
    {
        dim3 go(DIM / 128, TOKENS / 128);
        sgemm_kernel<<<go, 256>>>(attn, wo, out, TOKENS, DIM, DIM);
    }
}

// round 6
// speedup vs baseline: 1.3304x; 1.3304x over previous
#include <cuda_runtime.h>
#include <cuda_bf16.h>
#include <math.h>
#include <stdint.h>

// Problem constants
#define BSZ 2
#define SEQ 2048
#define DIM 4096
#define NH 32
#define NKV 8
#define HD 128
#define TOKENS (BSZ*SEQ)   // 4096
#define K3 12288           // 3 * DIM (hi|hi|lo concat)

// ---------------------------------------------------------------------------
// Scratch (device globals — no allocation allowed)
// ---------------------------------------------------------------------------
__device__ float g_xq[(size_t)TOKENS * NH * HD];    // 4096 x 4096
__device__ float g_xk[(size_t)TOKENS * NKV * HD];   // 4096 x 1024
__device__ float g_xv[(size_t)TOKENS * NKV * HD];   // 4096 x 1024
__device__ float g_attn[(size_t)TOKENS * NH * HD];  // 4096 x 4096

__device__ __nv_bfloat16 g_x3  [(size_t)TOKENS * K3];  // x split    [4096,12288]
__device__ __nv_bfloat16 g_at3 [(size_t)TOKENS * K3];  // attn split
__device__ __nv_bfloat16 g_wq3 [(size_t)4096 * K3];    // wq^T split [N,K3]
__device__ __nv_bfloat16 g_wk3 [(size_t)1024 * K3];
__device__ __nv_bfloat16 g_wv3 [(size_t)1024 * K3];
__device__ __nv_bfloat16 g_wo3 [(size_t)4096 * K3];

// ---------------------------------------------------------------------------
// PTX helpers (sm_80+ portable: cp.async / ldmatrix / mma.sync)
// ---------------------------------------------------------------------------
__device__ __forceinline__ uint32_t smem_u32(const void* p) {
    uint32_t a;
    asm("{ .reg .u64 t; cvta.to.shared.u64 t, %1; cvt.u32.u64 %0, t; }" : "=r"(a) : "l"(p));
    return a;
}
__device__ __forceinline__ void cp16(uint32_t s, const void* g) {
    asm volatile("cp.async.cg.shared.global [%0], [%1], 16;" :: "r"(s), "l"(g) : "memory");
}
__device__ __forceinline__ void cp_commit() {
    asm volatile("cp.async.commit_group;" ::: "memory");
}
template<int N> __device__ __forceinline__ void cp_wait() {
    asm volatile("cp.async.wait_group %0;" :: "n"(N) : "memory");
}
__device__ __forceinline__ void ldm_x4(uint32_t* r, uint32_t addr) {
    asm volatile("ldmatrix.sync.aligned.m8n8.x4.shared.b16 {%0,%1,%2,%3}, [%4];"
                 : "=r"(r[0]), "=r"(r[1]), "=r"(r[2]), "=r"(r[3]) : "r"(addr));
}
__device__ __forceinline__ void mma_bf16(float* d, const uint32_t* a, const uint32_t* b) {
    asm volatile(
        "mma.sync.aligned.m16n8k16.row.col.f32.bf16.bf16.f32 "
        "{%0,%1,%2,%3}, {%4,%5,%6,%7}, {%8,%9}, {%0,%1,%2,%3};"
        : "+f"(d[0]), "+f"(d[1]), "+f"(d[2]), "+f"(d[3])
        : "r"(a[0]), "r"(a[1]), "r"(a[2]), "r"(a[3]), "r"(b[0]), "r"(b[1]));
}

// ---------------------------------------------------------------------------
// Split/convert kernels
// ---------------------------------------------------------------------------
// Activation split: A[M,4096] f32 -> A3[M,12288] bf16 = [hi | hi | lo]
__global__ void split_act_kernel(const float* __restrict__ A,
                                 __nv_bfloat16* __restrict__ A3, int total)
{
    int i = blockIdx.x * blockDim.x + threadIdx.x;
    if (i >= total) return;
    int m = i >> 12;          // /4096
    int k = i & 4095;
    float v = A[i];
    __nv_bfloat16 hi = __float2bfloat16(v);
    __nv_bfloat16 lo = __float2bfloat16(v - __bfloat162float(hi));
    size_t base = (size_t)m * K3;
    A3[base + k]        = hi;
    A3[base + 4096 + k] = hi;
    A3[base + 8192 + k] = lo;
}

// Weight transpose+split: W[4096,N] f32 -> W3[N,12288] bf16 = [hi | lo | hi]
__global__ void transpose_split_kernel(const float* __restrict__ W,
                                       __nv_bfloat16* __restrict__ W3, int N)
{
    __shared__ float t[32][33];
    int k0 = blockIdx.x * 32, n0 = blockIdx.y * 32;
    int tx = threadIdx.x, ty = threadIdx.y;   // 32 x 8
    #pragma unroll
    for (int j = 0; j < 4; j++)
        t[ty + j * 8][tx] = W[(size_t)(k0 + ty + j * 8) * N + n0 + tx];
    __syncthreads();
    #pragma unroll
    for (int j = 0; j < 4; j++) {
        int n = n0 + ty + j * 8;
        int k = k0 + tx;
        float v = t[tx][ty + j * 8];
        __nv_bfloat16 hi = __float2bfloat16(v);
        __nv_bfloat16 lo = __float2bfloat16(v - __bfloat162float(hi));
        size_t base = (size_t)n * K3;
        W3[base + k]        = hi;
        W3[base + 4096 + k] = lo;
        W3[base + 8192 + k] = hi;
    }
}

// ---------------------------------------------------------------------------
// HMMA GEMM: C[M,N] = A3[M,K3] . B3[N,K3]^T   (bf16 in, fp32 out)
// BM=BN=128, BK=64, 256 threads (8 warps, warp tile 32x64), 2-stage cp.async.
// Smem row = 64 bf16 = 128B; chunk swizzle c^ (row&7) -> conflict-free ldmatrix.
// ---------------------------------------------------------------------------
#define HG_SMEM (64 * 1024)
#define NKC (K3 / 64)   // 192

__global__ __launch_bounds__(256) void hgemm_kernel(
    const __nv_bfloat16* __restrict__ A3,
    const __nv_bfloat16* __restrict__ B3,
    float* __restrict__ C, int N)
{
    extern __shared__ char smraw[];
    const uint32_t sbase = smem_u32(smraw);   // A0 | B0 | A1 | B1, 16KB each

    const int tid  = threadIdx.x;
    const int lane = tid & 31, warp = tid >> 5;
    const int wm = warp & 3;      // 0..3 -> m offset wm*32
    const int wn = warp >> 2;     // 0..1 -> n offset wn*64
    const int m0 = blockIdx.y * 128;
    const int n0 = blockIdx.x * 128;

    // loader: each thread owns rows lrow, lrow+32, +64, +96 at 16B-chunk lc
    const int lrow = tid >> 3;    // 0..31
    const int lc   = tid & 7;     // 0..7
    const __nv_bfloat16* gA = A3 + (size_t)(m0 + lrow) * K3 + lc * 8;
    const __nv_bfloat16* gB = B3 + (size_t)(n0 + lrow) * K3 + lc * 8;
    uint32_t soff[4];
    #pragma unroll
    for (int i = 0; i < 4; i++) {
        int row = lrow + 32 * i;
        soff[i] = row * 128 + ((lc ^ (row & 7)) * 16);
    }

    auto load_chunk = [&](int buf, int kc) {
        uint32_t sA = sbase + buf * 32768;
        uint32_t sB = sA + 16384;
        size_t koff = (size_t)kc * 64;
        #pragma unroll
        for (int i = 0; i < 4; i++) {
            cp16(sA + soff[i], gA + (size_t)(32 * i) * K3 + koff);
            cp16(sB + soff[i], gB + (size_t)(32 * i) * K3 + koff);
        }
    };

    float d[2][8][4];
    #pragma unroll
    for (int mi = 0; mi < 2; mi++)
        #pragma unroll
        for (int ni = 0; ni < 8; ni++)
            #pragma unroll
            for (int j = 0; j < 4; j++) d[mi][ni][j] = 0.f;

    load_chunk(0, 0);
    cp_commit();

    // precomputed ldmatrix row/col pieces
    const int aRow0 = wm * 32 + (lane & 15);        // + mi*16
    const int aSel  = lane >> 4;                     // k-half select
    const int bRow0 = wn * 64 + ((lane >> 4) & 1) * 8 + (lane & 7);  // + p*16
    const int bSel  = (lane >> 3) & 1;

    for (int kc = 0; kc < NKC; kc++) {
        if (kc + 1 < NKC) {
            load_chunk((kc + 1) & 1, kc + 1);
            cp_commit();
            cp_wait<1>();
        } else {
            cp_wait<0>();
        }
        __syncthreads();

        uint32_t sA = sbase + (kc & 1) * 32768;
        uint32_t sB = sA + 16384;

        #pragma unroll
        for (int ks = 0; ks < 4; ks++) {
            uint32_t aF[2][4];
            #pragma unroll
            for (int mi = 0; mi < 2; mi++) {
                int row = aRow0 + mi * 16;
                uint32_t c = (uint32_t)((ks * 2 + aSel) ^ (row & 7));
                ldm_x4(aF[mi], sA + row * 128 + c * 16);
            }
            uint32_t bF[8][2];
            #pragma unroll
            for (int p = 0; p < 4; p++) {
                int row = bRow0 + p * 16;
                uint32_t c = (uint32_t)((ks * 2 + bSel) ^ (row & 7));
                uint32_t r[4];
                ldm_x4(r, sB + row * 128 + c * 16);
                bF[2*p][0] = r[0]; bF[2*p][1] = r[1];
                bF[2*p+1][0] = r[2]; bF[2*p+1][1] = r[3];
            }
            #pragma unroll
            for (int mi = 0; mi < 2; mi++)
                #pragma unroll
                for (int ni = 0; ni < 8; ni++)
                    mma_bf16(d[mi][ni], aF[mi], bF[ni]);
        }
        __syncthreads();
    }

    // epilogue
    #pragma unroll
    for (int mi = 0; mi < 2; mi++) {
        int r0 = m0 + wm * 32 + mi * 16 + (lane >> 2);
        #pragma unroll
        for (int ni = 0; ni < 8; ni++) {
            int col = n0 + wn * 64 + ni * 8 + (lane & 3) * 2;
            *(float2*)&C[(size_t)r0 * N + col]       = make_float2(d[mi][ni][0], d[mi][ni][1]);
            *(float2*)&C[(size_t)(r0 + 8) * N + col] = make_float2(d[mi][ni][2], d[mi][ni][3]);
        }
    }
}

// ---------------------------------------------------------------------------
// RoPE: in-place on [TOKENS, H, 128] tensor.
// ---------------------------------------------------------------------------
__global__ void rope_kernel(float* __restrict__ t,
                            const float* __restrict__ fc,
                            const float* __restrict__ fs, int H, int total)
{
    int i = blockIdx.x * blockDim.x + threadIdx.x;
    if (i >= total) return;
    int half = i & 63;
    int h    = (i >> 6) % H;
    int tok  = i / (64 * H);
    int s    = tok & (SEQ - 1);
    float c  = fc[s * 64 + half];
    float sn = fs[s * 64 + half];
    float* p = t + (((size_t)tok * H + h) * HD) + 2 * half;
    float a = p[0], b = p[1];
    p[0] = a * c - b * sn;
    p[1] = a * sn + b * c;
}

// ---------------------------------------------------------------------------
// Causal flash attention, fp32, GQA (unchanged — passed in R1)
// ---------------------------------------------------------------------------
__global__ __launch_bounds__(256) void flash_kernel(
    const float* __restrict__ q, const float* __restrict__ k,
    const float* __restrict__ v, float* __restrict__ o)
{
    constexpr int BM = 64, BN = 32, D = HD;
    __shared__ float Ks[BN][D];
    __shared__ float Vs[BN][D];

    const int m0 = blockIdx.x * BM;
    const int h  = blockIdx.y;
    const int b  = blockIdx.z;
    const int kh = h >> 2;
    const int tid = threadIdx.x;
    const int row = tid >> 2;
    const int c4  = tid & 3;
    const int qrow = m0 + row;

    float qreg[32];
    {
        const float* qp = q + (((size_t)b * SEQ + qrow) * NH + h) * D + c4 * 32;
        #pragma unroll
        for (int d = 0; d < 32; d += 4) {
            float4 t = *(const float4*)(qp + d);
            qreg[d] = t.x; qreg[d+1] = t.y; qreg[d+2] = t.z; qreg[d+3] = t.w;
        }
    }

    float acc[32];
    #pragma unroll
    for (int d = 0; d < 32; d++) acc[d] = 0.f;
    float m = -INFINITY, l = 0.f;
    const float scale = 0.08838834764831845f;

    for (int j0 = 0; j0 < m0 + BM; j0 += BN) {
        {
            int base = tid * 16;
            int tr = base >> 7, tc = base & 127;
            const float* kp = k + (((size_t)b * SEQ + j0 + tr) * NKV + kh) * D + tc;
            const float* vp = v + (((size_t)b * SEQ + j0 + tr) * NKV + kh) * D + tc;
            #pragma unroll
            for (int u = 0; u < 16; u += 4) {
                *(float4*)&Ks[tr][tc + u] = *(const float4*)(kp + u);
                *(float4*)&Vs[tr][tc + u] = *(const float4*)(vp + u);
            }
        }
        __syncthreads();

        float s[BN];
        float tile_max = -INFINITY;
        #pragma unroll
        for (int j = 0; j < BN; j++) {
            float p = 0.f;
            const float4* kr = (const float4*)&Ks[j][c4 * 32];
            #pragma unroll
            for (int d4 = 0; d4 < 8; d4++) {
                float4 kv = kr[d4];
                p += qreg[4*d4+0]*kv.x + qreg[4*d4+1]*kv.y
                   + qreg[4*d4+2]*kv.z + qreg[4*d4+3]*kv.w;
            }
            p += __shfl_xor_sync(0xffffffffu, p, 1);
            p += __shfl_xor_sync(0xffffffffu, p, 2);
            p *= scale;
            if (j0 + j > qrow) p = -INFINITY;
            s[j] = p;
            tile_max = fmaxf(tile_max, p);
        }

        float m_new = fmaxf(m, tile_max);
        float corr = __expf(m - m_new);
        l *= corr;
        #pragma unroll
        for (int d = 0; d < 32; d++) acc[d] *= corr;

        #pragma unroll
        for (int j = 0; j < BN; j++) {
            float p = __expf(s[j] - m_new);
            l += p;
            const float4* vr = (const float4*)&Vs[j][c4 * 32];
            #pragma unroll
            for (int d4 = 0; d4 < 8; d4++) {
                float4 vv = vr[d4];
                acc[4*d4+0] += p * vv.x;
                acc[4*d4+1] += p * vv.y;
                acc[4*d4+2] += p * vv.z;
                acc[4*d4+3] += p * vv.w;
            }
        }
        m = m_new;
        __syncthreads();
    }

    float inv = 1.f / l;
    float* op = o + (((size_t)b * SEQ + qrow) * NH + h) * D + c4 * 32;
    #pragma unroll
    for (int d = 0; d < 32; d += 4) {
        float4 t = make_float4(acc[d]*inv, acc[d+1]*inv, acc[d+2]*inv, acc[d+3]*inv);
        *(float4*)(op + d) = t;
    }
}

// ---------------------------------------------------------------------------
extern "C" void kernel_launch(void* const* d_in, const int* in_sizes, int n_in,
                              void* d_out, int out_size)
{
    const float* x  = (const float*)d_in[0];
    const float* wq = (const float*)d_in[1];
    const float* wk = (const float*)d_in[2];
    const float* wv = (const float*)d_in[3];
    const float* wo = (const float*)d_in[4];
    const float* fc = (const float*)d_in[7];
    const float* fs = (const float*)d_in[8];
    float* out = (float*)d_out;

    float *xq, *xk, *xv, *attn;
    __nv_bfloat16 *x3, *at3, *wq3, *wk3, *wv3, *wo3;
    cudaGetSymbolAddress((void**)&xq,   g_xq);
    cudaGetSymbolAddress((void**)&xk,   g_xk);
    cudaGetSymbolAddress((void**)&xv,   g_xv);
    cudaGetSymbolAddress((void**)&attn, g_attn);
    cudaGetSymbolAddress((void**)&x3,   g_x3);
    cudaGetSymbolAddress((void**)&at3,  g_at3);
    cudaGetSymbolAddress((void**)&wq3,  g_wq3);
    cudaGetSymbolAddress((void**)&wk3,  g_wk3);
    cudaGetSymbolAddress((void**)&wv3,  g_wv3);
    cudaGetSymbolAddress((void**)&wo3,  g_wo3);

    cudaFuncSetAttribute(hgemm_kernel, cudaFuncAttributeMaxDynamicSharedMemorySize,
                         HG_SMEM);

    // Splits / transposes
    {
        int total = TOKENS * DIM;
        split_act_kernel<<<(total + 255) / 256, 256>>>(x, x3, total);
        dim3 blk(32, 8);
        transpose_split_kernel<<<dim3(128, 128), blk>>>(wq, wq3, 4096);
        transpose_split_kernel<<<dim3(128,  32), blk>>>(wk, wk3, 1024);
        transpose_split_kernel<<<dim3(128,  32), blk>>>(wv, wv3, 1024);
        transpose_split_kernel<<<dim3(128, 128), blk>>>(wo, wo3, 4096);
    }

    // QKV projections (HMMA)
    hgemm_kernel<<<dim3(4096/128, TOKENS/128), 256, HG_SMEM>>>(x3, wq3, xq, 4096);
    hgemm_kernel<<<dim3(1024/128, TOKENS/128), 256, HG_SMEM>>>(x3, wk3, xk, 1024);
    hgemm_kernel<<<dim3(1024/128, TOKENS/128), 256, HG_SMEM>>>(x3, wv3, xv, 1024);

    // RoPE
    {
        int tq = TOKENS * NH * 64;
        rope_kernel<<<(tq + 255) / 256, 256>>>(xq, fc, fs, NH, tq);
        int tk = TOKENS * NKV * 64;
        rope_kernel<<<(tk + 255) / 256, 256>>>(xk, fc, fs, NKV, tk);
    }

    // Causal flash attention (start_pos = 0, cache zero => keys/values = xk/xv)
    {
        dim3 g(SEQ / 64, NH, BSZ);
        flash_kernel<<<g, 256>>>(xq, xk, xv, attn);
    }

    // Output projection (HMMA)
    {
        int total = TOKENS * DIM;
        split_act_kernel<<<(total + 255) / 256, 256>>>(attn, at3, total);
        hgemm_kernel<<<dim3(4096/128, TOKENS/128), 256, HG_SMEM>>>(at3, wo3, out, 4096);
    }
}